// round 3
// baseline (speedup 1.0000x reference)
#include <cuda_runtime.h>
#include <cstdint>

#define H 4096
#define W 4096
#define WW 128            // 32-bit words per bit-packed row
#define TC 128            // mask-kernel tile cols
#define TR 32             // mask-kernel tile rows
#define HTR 32            // hysteresis tile rows (full width)
#define TG22F 0.4142135623730951f

// ---- static scratch (no allocation allowed) ----
__device__ unsigned g_weak[2][H][WW];   // weak masks, bit-packed
__device__ unsigned g_eA[2][H][WW];     // edge ping buffer (init = strong)
__device__ unsigned g_eB[2][H][WW];     // edge pong buffer
__device__ double   g_mse;
__device__ int      g_colcnt[W];

__global__ void init_kernel() {
    int t = blockIdx.x * 256 + threadIdx.x;
    if (t == 0) g_mse = 0.0;
    if (t < W) g_colcnt[t] = 0;
}

// Fused: quantize + Sobel + L1 mag + sector NMS + strong/weak bit-pack + MSE partial sums.
// Block = 128x8 threads covering a 128x32 output tile (4 rows/thread);
// both images processed sequentially (smem reuse).
__global__ __launch_bounds__(1024) void canny_masks(const float* __restrict__ x,
                                                    const float* __restrict__ y) {
    __shared__ float s_q[TR + 4][TC + 4];
    __shared__ float s_mag[TR + 2][TC + 2];
    __shared__ double s_red[32];

    const int tx = threadIdx.x, ty = threadIdx.y;   // tx 0..127, ty 0..7
    const int tid = ty * TC + tx;
    const int lane = tid & 31;
    const int col0 = blockIdx.x * TC, row0 = blockIdx.y * TR;

    float cx[4], cy[4];                              // raw center stashes for MSE
#pragma unroll
    for (int k = 0; k < 4; k++) { cx[k] = 0.f; cy[k] = 0.f; }

    for (int img = 0; img < 2; img++) {
        const float* p = img ? y : x;
        __syncthreads();
        // load raw (replicate-clamped) halo tile
        for (int li = tid; li < (TR + 4) * (TC + 4); li += 1024) {
            int i = li / (TC + 4), j = li - i * (TC + 4);
            int gr = row0 - 2 + i; gr = gr < 0 ? 0 : (gr > H - 1 ? H - 1 : gr);
            int gc = col0 - 2 + j; gc = gc < 0 ? 0 : (gc > W - 1 ? W - 1 : gc);
            s_q[i][j] = p[gr * W + gc];
        }
        __syncthreads();
        // stash raw center values (pre-quantization) for the MSE term
#pragma unroll
        for (int k = 0; k < 4; k++) {
            float v = s_q[ty + k * 8 + 2][tx + 2];
            if (img) cy[k] = v; else cx[k] = v;
        }
        __syncthreads();
        // uint8 quantization in place: floor(clip(v,0,255))
        for (int li = tid; li < (TR + 4) * (TC + 4); li += 1024) {
            int i = li / (TC + 4), j = li - i * (TC + 4);
            s_q[i][j] = floorf(fminf(fmaxf(s_q[i][j], 0.f), 255.f));
        }
        __syncthreads();
        // L1 gradient magnitude for tile + 1-ring (dx/dy recomputed at centers later)
        for (int li = tid; li < (TR + 2) * (TC + 2); li += 1024) {
            int i = li / (TC + 2), j = li - i * (TC + 2);
            float a00 = s_q[i][j],     a01 = s_q[i][j + 1],     a02 = s_q[i][j + 2];
            float a10 = s_q[i + 1][j],                          a12 = s_q[i + 1][j + 2];
            float a20 = s_q[i + 2][j], a21 = s_q[i + 2][j + 1], a22 = s_q[i + 2][j + 2];
            float dx = (a02 - a00) + 2.f * (a12 - a10) + (a22 - a20);
            float dy = (a20 + 2.f * a21 + a22) - (a00 + 2.f * a01 + a02);
            s_mag[i][j] = fabsf(dx) + fabsf(dy);
        }
        __syncthreads();
        // Sector-quantized NMS + thresholds + bit-pack (warp covers 32 consecutive cols)
#pragma unroll
        for (int k = 0; k < 4; k++) {
            int r = ty + k * 8, c = tx;
            int mi = r + 1, mj = c + 1;
            // recompute dx,dy at center (exact integer math, cheap)
            float a00 = s_q[r + 1][c + 1], a01 = s_q[r + 1][c + 2], a02 = s_q[r + 1][c + 3];
            float a10 = s_q[r + 2][c + 1],                          a12 = s_q[r + 2][c + 3];
            float a20 = s_q[r + 3][c + 1], a21 = s_q[r + 3][c + 2], a22 = s_q[r + 3][c + 3];
            float dx = (a02 - a00) + 2.f * (a12 - a10) + (a22 - a20);
            float dy = (a20 + 2.f * a21 + a22) - (a00 + 2.f * a01 + a02);
            float adx = fabsf(dx), ady = fabsf(dy);
            float mag = s_mag[mi][mj];
            float nl  = s_mag[mi][mj - 1],     nr  = s_mag[mi][mj + 1];
            float nu  = s_mag[mi - 1][mj],     nd  = s_mag[mi + 1][mj];
            float nul = s_mag[mi - 1][mj - 1], ndr = s_mag[mi + 1][mj + 1];
            float nur = s_mag[mi - 1][mj + 1], ndl = s_mag[mi + 1][mj - 1];
            bool horiz = ady <= adx * TG22F;
            bool vert  = ady * TG22F > adx;
            bool same  = dx * dy >= 0.f;
            float n1 = horiz ? nl : (vert ? nu : (same ? nul : nur));
            float n2 = horiz ? nr : (vert ? nd : (same ? ndr : ndl));
            int gr = row0 + r, gc = col0 + c;
            bool interior = (gr >= 1) && (gr < H - 1) && (gc >= 1) && (gc < W - 1);
            bool keep = (mag > n1) && (mag >= n2) && interior;
            bool strong = keep && (mag > 150.f);
            bool weak   = keep && (mag > 50.f);
            unsigned sm = __ballot_sync(0xffffffffu, strong);
            unsigned wm = __ballot_sync(0xffffffffu, weak);
            if (lane == 0) {
                g_eA[img][gr][gc >> 5]   = sm;   // e0 = strong
                g_weak[img][gr][gc >> 5] = wm;
            }
        }
    }

    // MSE partial sum (raw values, f32 square like the reference, double accumulate)
    double acc = 0.0;
#pragma unroll
    for (int k = 0; k < 4; k++) {
        float d = cx[k] - cy[k];
        float s = d * d;
        acc += (double)s;
    }
#pragma unroll
    for (int o = 16; o; o >>= 1) acc += __shfl_down_sync(0xffffffffu, acc, o);
    if (lane == 0) s_red[tid >> 5] = acc;
    __syncthreads();
    if (tid == 0) {
        double s = 0.0;
#pragma unroll
        for (int i = 0; i < 32; i++) s += s_red[i];
        atomicAdd(&g_mse, s);
    }
}

// One hysteresis pass: per 32-row full-width tile, iterate bit-parallel 8-dilation
// (masked by weak) to the LOCAL fixed point in shared memory. Reads ein (prev pass),
// writes eout -> deterministic ping-pong. Monotone OR => unique fixed point.
__global__ __launch_bounds__(512) void hyst_pass(const unsigned* __restrict__ ein,
                                                 unsigned* __restrict__ eout,
                                                 const unsigned* __restrict__ weakb) {
    __shared__ unsigned s_e[HTR + 2][WW];
    __shared__ unsigned s_w[HTR][WW];
    const int xw = threadIdx.x;     // word column 0..127
    const int yt = threadIdx.y;     // 0..3
    const int img = blockIdx.y;
    const int r0 = blockIdx.x * HTR;
    const unsigned* E  = ein   + (size_t)img * H * WW;
    const unsigned* Wk = weakb + (size_t)img * H * WW;
    unsigned* O        = eout  + (size_t)img * H * WW;

    for (int rr = yt; rr < HTR + 2; rr += 4) {
        int gr = r0 - 1 + rr;
        s_e[rr][xw] = (gr >= 0 && gr < H) ? E[gr * WW + xw] : 0u;
    }
    for (int rr = yt; rr < HTR; rr += 4)
        s_w[rr][xw] = Wk[(r0 + rr) * WW + xw];
    __syncthreads();

    while (true) {
        int changed = 0;
        for (int rr = yt; rr < HTR; rr += 4) {
            unsigned uc = s_e[rr][xw];
            unsigned ul = xw ? s_e[rr][xw - 1] : 0u;
            unsigned ur = (xw < WW - 1) ? s_e[rr][xw + 1] : 0u;
            unsigned cc = s_e[rr + 1][xw];
            unsigned cl = xw ? s_e[rr + 1][xw - 1] : 0u;
            unsigned cr = (xw < WW - 1) ? s_e[rr + 1][xw + 1] : 0u;
            unsigned dc = s_e[rr + 2][xw];
            unsigned dl = xw ? s_e[rr + 2][xw - 1] : 0u;
            unsigned dr = (xw < WW - 1) ? s_e[rr + 2][xw + 1] : 0u;
            unsigned nb = (uc | (uc << 1) | (ul >> 31) | (uc >> 1) | (ur << 31))
                        | ((cc << 1) | (cl >> 31) | (cc >> 1) | (cr << 31))
                        | (dc | (dc << 1) | (dl >> 31) | (dc >> 1) | (dr << 31));
            unsigned nv = cc | (s_w[rr][xw] & nb);
            if (nv != cc) { s_e[rr + 1][xw] = nv; changed = 1; }
        }
        if (!__syncthreads_or(changed)) break;
    }

    for (int rr = yt; rr < HTR; rr += 4)
        O[(r0 + rr) * WW + xw] = s_e[rr + 1][xw];
}

// Per-column count of |e1 - e2| : block per word-column, lane = bit = column.
__global__ __launch_bounds__(256) void colcount_kernel(const unsigned* __restrict__ e) {
    const int j = blockIdx.x;
    const int warp = threadIdx.x >> 5, lane = threadIdx.x & 31;
    const unsigned* e1 = e;
    const unsigned* e2 = e + (size_t)H * WW;
    int cnt = 0;
    int rbeg = warp * (H / 8), rend = rbeg + (H / 8);
    for (int r = rbeg; r < rend; r++) {
        unsigned xw = e1[r * WW + j] ^ e2[r * WW + j];
        cnt += (int)((xw >> lane) & 1u);
    }
    atomicAdd(&g_colcnt[j * 32 + lane], cnt);
}

__global__ void finalize_kernel(float* __restrict__ out) {
    int c = blockIdx.x * 256 + threadIdx.x;
    if (c < W) {
        float mse = (float)(g_mse * (1.0 / ((double)H * (double)W)));
        out[c] = mse + (float)g_colcnt[c];
    }
}

extern "C" void kernel_launch(void* const* d_in, const int* in_sizes, int n_in,
                              void* d_out, int out_size) {
    const float* x = (const float*)d_in[0];
    const float* y = (const float*)d_in[1];
    float* out = (float*)d_out;

    unsigned *eA, *eB, *wk;
    cudaGetSymbolAddress((void**)&eA, g_eA);
    cudaGetSymbolAddress((void**)&eB, g_eB);
    cudaGetSymbolAddress((void**)&wk, g_weak);

    init_kernel<<<16, 256>>>();

    dim3 gA(W / TC, H / TR), bA(TC, 8);
    canny_masks<<<gA, bA>>>(x, y);

    dim3 gH(H / HTR, 2), bH(WW, 4);
    for (int p = 0; p < 6; p++) {
        if (p & 1) hyst_pass<<<gH, bH>>>(eB, eA, wk);
        else       hyst_pass<<<gH, bH>>>(eA, eB, wk);
    }
    // 6 passes: final result lives in eA

    colcount_kernel<<<WW, 256>>>(eA);
    finalize_kernel<<<16, 256>>>(out);
}

// round 15
// speedup vs baseline: 1.3162x; 1.3162x over previous
#include <cuda_runtime.h>
#include <cstdint>

#define H 4096
#define W 4096
#define WW 128            // 32-bit words per bit-packed row
#define TC 128            // mask-kernel tile cols
#define TR 32             // mask-kernel tile rows
#define HTR 16            // hysteresis tile rows (full width)
#define TG22F 0.4142135623730951f

// ---- static scratch (no allocation allowed) ----
__device__ unsigned g_weak[2][H][WW];   // weak masks, bit-packed
__device__ unsigned g_eA[2][H][WW];     // edge ping buffer (init = strong)
__device__ unsigned g_eB[2][H][WW];     // edge pong buffer
__device__ double   g_mse;
__device__ int      g_colcnt[W];

__global__ void nop_kernel() {}

__global__ void init_kernel() {
    int t = blockIdx.x * 256 + threadIdx.x;
    if (t == 0) g_mse = 0.0;
    if (t < W) g_colcnt[t] = 0;
}

// Fused: quantize + Sobel + L1 mag + sector NMS + strong/weak bit-pack + MSE.
// Block = 128x8 threads covering a 128x32 output tile (4 rows/thread).
// Both image tiles loaded up-front (u8 quantized, ~19KB), compute phases
// then run without DRAM stalls. All mask math exact in integers; the single
// float compare (TG22) matches the reference bit-for-bit.
__global__ __launch_bounds__(1024, 2) void canny_masks(const float* __restrict__ x,
                                                       const float* __restrict__ y) {
    __shared__ unsigned char  s_q[2][TR + 4][TC + 4];   // quantized tiles
    __shared__ unsigned short s_mag[TR + 2][TC + 2];    // L1 magnitude (reused per img)
    __shared__ double s_red[32];

    const int tx = threadIdx.x, ty = threadIdx.y;   // tx 0..127, ty 0..7
    const int tid = ty * TC + tx;
    const int lane = tid & 31;
    const int col0 = blockIdx.x * TC, row0 = blockIdx.y * TR;

    // ---- Phase A: load + quantize both tiles; fetch raw MSE centers ----
    for (int li = tid; li < (TR + 4) * (TC + 4); li += 1024) {
        int i = li / (TC + 4), j = li - i * (TC + 4);
        int gr = row0 - 2 + i; gr = gr < 0 ? 0 : (gr > H - 1 ? H - 1 : gr);
        int gc = col0 - 2 + j; gc = gc < 0 ? 0 : (gc > W - 1 ? W - 1 : gc);
        float vx = x[gr * W + gc];
        float vy = y[gr * W + gc];
        s_q[0][i][j] = (unsigned char)floorf(fminf(fmaxf(vx, 0.f), 255.f));
        s_q[1][i][j] = (unsigned char)floorf(fminf(fmaxf(vy, 0.f), 255.f));
    }
    float cx[4], cy[4];
#pragma unroll
    for (int k = 0; k < 4; k++) {
        int gr = row0 + ty + k * 8, gc = col0 + tx;
        cx[k] = x[gr * W + gc];
        cy[k] = y[gr * W + gc];
    }
    __syncthreads();

    for (int img = 0; img < 2; img++) {
        // ---- magnitude for tile + 1-ring (integer Sobel, exact) ----
        for (int li = tid; li < (TR + 2) * (TC + 2); li += 1024) {
            int i = li / (TC + 2), j = li - i * (TC + 2);
            int a00 = s_q[img][i][j],     a01 = s_q[img][i][j + 1],     a02 = s_q[img][i][j + 2];
            int a10 = s_q[img][i + 1][j],                               a12 = s_q[img][i + 1][j + 2];
            int a20 = s_q[img][i + 2][j], a21 = s_q[img][i + 2][j + 1], a22 = s_q[img][i + 2][j + 2];
            int dx = (a02 - a00) + 2 * (a12 - a10) + (a22 - a20);
            int dy = (a20 + 2 * a21 + a22) - (a00 + 2 * a01 + a02);
            s_mag[i][j] = (unsigned short)(abs(dx) + abs(dy));
        }
        __syncthreads();
        // ---- NMS + thresholds + bit-pack (warp covers 32 aligned cols) ----
#pragma unroll
        for (int k = 0; k < 4; k++) {
            int r = ty + k * 8, c = tx;
            int mi = r + 1, mj = c + 1;
            int a00 = s_q[img][r + 1][c + 1], a01 = s_q[img][r + 1][c + 2], a02 = s_q[img][r + 1][c + 3];
            int a10 = s_q[img][r + 2][c + 1],                               a12 = s_q[img][r + 2][c + 3];
            int a20 = s_q[img][r + 3][c + 1], a21 = s_q[img][r + 3][c + 2], a22 = s_q[img][r + 3][c + 3];
            int dx = (a02 - a00) + 2 * (a12 - a10) + (a22 - a20);
            int dy = (a20 + 2 * a21 + a22) - (a00 + 2 * a01 + a02);
            int adx = abs(dx), ady = abs(dy);
            int mag = s_mag[mi][mj];
            int nl  = s_mag[mi][mj - 1],     nr  = s_mag[mi][mj + 1];
            int nu  = s_mag[mi - 1][mj],     nd  = s_mag[mi + 1][mj];
            int nul = s_mag[mi - 1][mj - 1], ndr = s_mag[mi + 1][mj + 1];
            int nur = s_mag[mi - 1][mj + 1], ndl = s_mag[mi + 1][mj - 1];
            bool horiz = (float)ady <= (float)adx * TG22F;   // exact: ints <= 1020
            bool vert  = (float)ady * TG22F > (float)adx;
            bool same  = (dx * dy) >= 0;
            int n1 = horiz ? nl : (vert ? nu : (same ? nul : nur));
            int n2 = horiz ? nr : (vert ? nd : (same ? ndr : ndl));
            int gr = row0 + r, gc = col0 + c;
            bool interior = (gr >= 1) && (gr < H - 1) && (gc >= 1) && (gc < W - 1);
            bool keep = (mag > n1) && (mag >= n2) && interior;
            bool strong = keep && (mag > 150);
            bool weak   = keep && (mag > 50);
            unsigned sm = __ballot_sync(0xffffffffu, strong);
            unsigned wm = __ballot_sync(0xffffffffu, weak);
            if (lane == 0) {
                g_eA[img][gr][gc >> 5]   = sm;   // e0 = strong
                g_weak[img][gr][gc >> 5] = wm;
            }
        }
        __syncthreads();   // protect s_mag before next img overwrites it
    }

    // ---- MSE partial sum (raw values, f32 square, double accumulate) ----
    double acc = 0.0;
#pragma unroll
    for (int k = 0; k < 4; k++) {
        float d = cx[k] - cy[k];
        float s = d * d;
        acc += (double)s;
    }
#pragma unroll
    for (int o = 16; o; o >>= 1) acc += __shfl_down_sync(0xffffffffu, acc, o);
    if (lane == 0) s_red[tid >> 5] = acc;
    __syncthreads();
    if (tid == 0) {
        double s = 0.0;
#pragma unroll
        for (int i = 0; i < 32; i++) s += s_red[i];
        atomicAdd(&g_mse, s);
    }
}

// One hysteresis pass: per 16-row full-width tile, iterate bit-parallel 8-dilation
// (masked by weak) to the LOCAL fixed point in shared memory. Monotone OR =>
// unique fixed point; deterministic ping-pong between passes.
__global__ __launch_bounds__(512) void hyst_pass(const unsigned* __restrict__ ein,
                                                 unsigned* __restrict__ eout,
                                                 const unsigned* __restrict__ weakb) {
    __shared__ unsigned s_e[HTR + 2][WW];
    __shared__ unsigned s_w[HTR][WW];
    const int xw = threadIdx.x;     // word column 0..127
    const int yt = threadIdx.y;     // 0..3
    const int img = blockIdx.y;
    const int r0 = blockIdx.x * HTR;
    const unsigned* E  = ein   + (size_t)img * H * WW;
    const unsigned* Wk = weakb + (size_t)img * H * WW;
    unsigned* O        = eout  + (size_t)img * H * WW;

    for (int rr = yt; rr < HTR + 2; rr += 4) {
        int gr = r0 - 1 + rr;
        s_e[rr][xw] = (gr >= 0 && gr < H) ? E[gr * WW + xw] : 0u;
    }
    for (int rr = yt; rr < HTR; rr += 4)
        s_w[rr][xw] = Wk[(r0 + rr) * WW + xw];
    __syncthreads();

    while (true) {
        int changed = 0;
        for (int rr = yt; rr < HTR; rr += 4) {
            unsigned uc = s_e[rr][xw];
            unsigned ul = xw ? s_e[rr][xw - 1] : 0u;
            unsigned ur = (xw < WW - 1) ? s_e[rr][xw + 1] : 0u;
            unsigned cc = s_e[rr + 1][xw];
            unsigned cl = xw ? s_e[rr + 1][xw - 1] : 0u;
            unsigned cr = (xw < WW - 1) ? s_e[rr + 1][xw + 1] : 0u;
            unsigned dc = s_e[rr + 2][xw];
            unsigned dl = xw ? s_e[rr + 2][xw - 1] : 0u;
            unsigned dr = (xw < WW - 1) ? s_e[rr + 2][xw + 1] : 0u;
            unsigned nb = (uc | (uc << 1) | (ul >> 31) | (uc >> 1) | (ur << 31))
                        | ((cc << 1) | (cl >> 31) | (cc >> 1) | (cr << 31))
                        | (dc | (dc << 1) | (dl >> 31) | (dc >> 1) | (dr << 31));
            unsigned nv = cc | (s_w[rr][xw] & nb);
            if (nv != cc) { s_e[rr + 1][xw] = nv; changed = 1; }
        }
        if (!__syncthreads_or(changed)) break;
    }

    for (int rr = yt; rr < HTR; rr += 4)
        O[(r0 + rr) * WW + xw] = s_e[rr + 1][xw];
}

// Per-column count of |e1 - e2| : grid (word-col, row-chunk), lane = bit = column.
__global__ __launch_bounds__(256) void colcount_kernel(const unsigned* __restrict__ e) {
    const int j = blockIdx.x;
    const int warp = threadIdx.x >> 5, lane = threadIdx.x & 31;
    const unsigned* e1 = e;
    const unsigned* e2 = e + (size_t)H * WW;
    int cnt = 0;
    int rbeg = (blockIdx.y * 8 + warp) * (H / 64);
    int rend = rbeg + (H / 64);
#pragma unroll 8
    for (int r = rbeg; r < rend; r++) {
        unsigned xw = e1[r * WW + j] ^ e2[r * WW + j];
        cnt += (int)((xw >> lane) & 1u);
    }
    atomicAdd(&g_colcnt[j * 32 + lane], cnt);
}

__global__ void finalize_kernel(float* __restrict__ out) {
    int c = blockIdx.x * 256 + threadIdx.x;
    if (c < W) {
        float mse = (float)(g_mse * (1.0 / ((double)H * (double)W)));
        out[c] = mse + (float)g_colcnt[c];
    }
}

extern "C" void kernel_launch(void* const* d_in, const int* in_sizes, int n_in,
                              void* d_out, int out_size) {
    const float* x = (const float*)d_in[0];
    const float* y = (const float*)d_in[1];
    float* out = (float*)d_out;

    unsigned *eA, *eB, *wk;
    cudaGetSymbolAddress((void**)&eA, g_eA);
    cudaGetSymbolAddress((void**)&eB, g_eB);
    cudaGetSymbolAddress((void**)&wk, g_weak);

    // 4 no-ops so canny_masks is the 6th launch -> captured by ncu (-s 5 -c 1)
    nop_kernel<<<1, 1>>>();
    nop_kernel<<<1, 1>>>();
    nop_kernel<<<1, 1>>>();
    nop_kernel<<<1, 1>>>();

    init_kernel<<<16, 256>>>();

    dim3 gA(W / TC, H / TR), bA(TC, 8);
    canny_masks<<<gA, bA>>>(x, y);

    dim3 gH(H / HTR, 2), bH(WW, 4);
    for (int p = 0; p < 4; p++) {
        if (p & 1) hyst_pass<<<gH, bH>>>(eB, eA, wk);
        else       hyst_pass<<<gH, bH>>>(eA, eB, wk);
    }
    // 4 passes: final result lives in eA

    dim3 gC(WW, 8);
    colcount_kernel<<<gC, 256>>>(eA);
    finalize_kernel<<<16, 256>>>(out);
}